// round 8
// baseline (speedup 1.0000x reference)
#include <cuda_runtime.h>
#include <cuda_fp16.h>
#include <cstdint>
#include <math.h>

constexpr int C = 1024;

// ---- smem byte offsets ----
constexpr uint32_t XB   = 0;        // X: 128 rows x 272B, in-place all stages
constexpr uint32_t W0   = 34816;    // weight buffer 0
constexpr uint32_t W1   = 69632;    // weight buffer 1
constexpr uint32_t MISC = 104448;
constexpr uint32_t SMEM_DYN = 106560;
constexpr uint32_t RSB = 272;

// ---- weight arena: per-stage [K rows x 128 cols] fp16 ----
constexpr uint32_t GA1 = 0;        // nb1_0|nb1_1      K=128
constexpr uint32_t GA2 = 34816;    // blockdiag nb2    K=128
constexpr uint32_t GA3 = 69632;    // We|Wa            K=64
constexpr uint32_t GA4 = 87040;    // GRU r|z          K=128
constexpr uint32_t GA5 = 121856;   // blockdiag in|hn  K=128
__device__ __align__(16) unsigned char g_wb[156672];
__device__ float g_adj[2 * C];

__device__ __forceinline__ float clip5f(float v) { return fminf(fmaxf(v, -5.f), 5.f); }
__device__ __forceinline__ float sigmf(float v) { return 1.f / (1.f + expf(-v)); }

__device__ __forceinline__ uint32_t smem_u32(const void* p) {
    uint32_t a;
    asm("{ .reg .u64 t; cvta.to.shared.u64 t, %1; cvt.u32.u64 %0, t; }" : "=r"(a) : "l"(p));
    return a;
}
__device__ __forceinline__ void ldsm4(uint32_t* r, uint32_t a) {
    asm volatile("ldmatrix.sync.aligned.m8n8.x4.shared.b16 {%0,%1,%2,%3}, [%4];"
                 : "=r"(r[0]), "=r"(r[1]), "=r"(r[2]), "=r"(r[3]) : "r"(a));
}
__device__ __forceinline__ void ldsm4t(uint32_t* r, uint32_t a) {
    asm volatile("ldmatrix.sync.aligned.m8n8.x4.trans.shared.b16 {%0,%1,%2,%3}, [%4];"
                 : "=r"(r[0]), "=r"(r[1]), "=r"(r[2]), "=r"(r[3]) : "r"(a));
}
__device__ __forceinline__ void mma16816(float* d, const uint32_t* a, const uint32_t* b) {
    asm volatile("mma.sync.aligned.m16n8k16.row.col.f32.f16.f16.f32 "
                 "{%0,%1,%2,%3}, {%4,%5,%6,%7}, {%8,%9}, {%0,%1,%2,%3};"
                 : "+f"(d[0]), "+f"(d[1]), "+f"(d[2]), "+f"(d[3])
                 : "r"(a[0]), "r"(a[1]), "r"(a[2]), "r"(a[3]), "r"(b[0]), "r"(b[1]));
}
__device__ __forceinline__ void cpa16(uint32_t dst, const void* src) {
    asm volatile("cp.async.cg.shared.global [%0], [%1], 16;" :: "r"(dst), "l"(src));
}
__device__ __forceinline__ void cpa_commit() { asm volatile("cp.async.commit_group;" ::: "memory"); }
__device__ __forceinline__ void cpa_wait0()  { asm volatile("cp.async.wait_group 0;" ::: "memory"); }

__device__ __forceinline__ uint32_t packH2(float f0, float f1) {
    uint32_t h;
    asm("cvt.rn.f16x2.f32 %0, %1, %2;" : "=r"(h) : "f"(f1), "f"(f0));
    return h;
}
__device__ __forceinline__ void storeH2(uint32_t addr, float f0, float f1) {
    uint32_t h = packH2(f0, f1);
    asm volatile("st.shared.b32 [%0], %1;" :: "r"(addr), "r"(h));
}

// ---------------- adj precompute (sparse) ------------------------------------------------
__global__ void adj_kernel(const int* __restrict__ qt, const float* __restrict__ onehot,
                           const float* __restrict__ graphs) {
    __shared__ int nnz;
    __shared__ int idxs[1024];
    __shared__ float wts[1024];
    __shared__ float denom;
    int d = threadIdx.x, k = blockIdx.x;
    const float* a0 = onehot + (size_t)qt[0] * C;
    float a = a0[d];
    if (d == 0) nnz = 0;
    __syncthreads();
    if (a != 0.f) { int p = atomicAdd(&nnz, 1); idxs[p] = d; wts[p] = a; }
    __syncthreads();
    if (d == 0) {
        float s = 0.f;
        for (int i = 0; i < nnz; ++i) s += wts[i];
        denom = fmaxf(s, 1.f);
    }
    __syncthreads();
    float s = 0.f;
    int m = nnz;
    for (int i = 0; i < m; ++i)
        s = fmaf(wts[i], graphs[((size_t)k * C + idxs[i]) * C + d], s);
    g_adj[k * C + d] = clip5f(s / denom);
}

// ---------------- weight prep: merged [K,128] fp16 images --------------------------------
__global__ void prep_kernel(const float* __restrict__ Wn1, const float* __restrict__ Wn2,
                            const float* __restrict__ We,  const float* __restrict__ Wa,
                            const float* __restrict__ Wih, const float* __restrict__ Whh) {
    int i = blockIdx.x * 256 + threadIdx.x;
    if (i >= 73728) return;
    int j; uint32_t base; float w = 0.f;
    if (i < 16384) {
        j = i; base = GA1;
        int k = j >> 7, n = j & 127;
        if (n < 64) w = Wn1[(size_t)(128 + k) * 64 + n];
        else        w = Wn1[(size_t)(256 + 128 + k) * 64 + (n - 64)];
    } else if (i < 32768) {
        j = i - 16384; base = GA2;
        int k = j >> 7, n = j & 127;
        if (k < 64 && n < 64)        w = Wn2[(size_t)k * 64 + n];
        else if (k >= 64 && n >= 64) w = Wn2[(size_t)k * 64 + (n - 64)];
    } else if (i < 40960) {
        j = i - 32768; base = GA3;
        int k = j >> 7, n = j & 127;
        w = (n < 64) ? We[(size_t)k * 64 + n] : Wa[(size_t)k * 64 + (n - 64)];
    } else if (i < 57344) {
        j = i - 40960; base = GA4;
        int k = j >> 7, n = j & 127;
        w = (k < 64) ? Wih[(size_t)k * 192 + n] : Whh[(size_t)(k - 64) * 192 + n];
    } else {
        j = i - 57344; base = GA5;
        int k = j >> 7, n = j & 127;
        if (k < 64 && n < 64)        w = Wih[(size_t)k * 192 + 128 + n];
        else if (k >= 64 && n >= 64) w = Whh[(size_t)(k - 64) * 192 + 128 + (n - 64)];
    }
    int k = j >> 7, n = j & 127;
    *(__half*)(g_wb + base + (uint32_t)k * RSB + n * 2) = __float2half_rn(w);
}

// ---- stage GEMM, 4(M)x2(N) warp split: warp computes 32 rows x (2x32-col bundles) ----
// d[mt*8 + nb]: mt in {0,1} (16-row subtile), nb 0..3 -> cols 32ng+8nb.., nb 4..7 -> +64.
template <int KD>
__device__ __forceinline__ void mma_stage(uint32_t aBase, uint32_t wbuf,
                                          float d[16][4], int mw, int ng, int lane) {
    const int lrow = (lane & 7) + ((lane & 8) ? 8 : 0);
    const int lhi8 = (lane & 16) ? 8 : 0;
    const uint32_t aA = aBase + (uint32_t)(32 * mw + lrow) * RSB + lhi8 * 2;
    const uint32_t wOff = wbuf + (uint32_t)lrow * RSB + lhi8 * 2 + (uint32_t)(64 * ng);
#pragma unroll
    for (int kc = 0; kc < KD / 16; ++kc) {
        uint32_t a0[4], a1[4];
        ldsm4(a0, aA + kc * 32);
        ldsm4(a1, aA + 16 * RSB + kc * 32);
        uint32_t bF[4][4];
        uint32_t wb = wOff + (uint32_t)kc * 16 * RSB;
        ldsm4t(bF[0], wb);
        ldsm4t(bF[1], wb + 32);
        ldsm4t(bF[2], wb + 128);
        ldsm4t(bF[3], wb + 160);
#pragma unroll
        for (int nb = 0; nb < 8; ++nb) {
            const uint32_t* bp = &bF[(nb >> 2) * 2 + ((nb & 3) >> 1)][(nb & 1) * 2];
            mma16816(d[nb], a0, bp);
            mma16816(d[8 + nb], a1, bp);
        }
    }
}

__device__ __forceinline__ void prefetchW(uint32_t dst, uint32_t gsrc, int bytes, int tid) {
    const unsigned char* s = g_wb + gsrc;
    for (int o = tid * 16; o < bytes; o += 256 * 16) cpa16(dst + o, s + o);
    cpa_commit();
}

// ---------------- main fused kernel ------------------------------------------------------
__global__ void __launch_bounds__(256, 2)
fused_kernel(const int* __restrict__ qt, const float* __restrict__ ht,
             const float* __restrict__ onehot, const float* __restrict__ kc,
             const float* __restrict__ nwp,
             const float* __restrict__ Ws1, const float* __restrict__ bs1,
             const float* __restrict__ Ws2, const float* __restrict__ bs2,
             const float* __restrict__ bn1, const float* __restrict__ bn2,
             const float* __restrict__ ea,  const float* __restrict__ be,
             const float* __restrict__ ba,  const float* __restrict__ bih,
             const float* __restrict__ bhh, const float* __restrict__ Wp,
             const float* __restrict__ bp, float* __restrict__ out) {
    extern __shared__ __align__(16) char sm[];
    const uint32_t smb = smem_u32(sm);

    const int tid = threadIdx.x;
    const int warp = tid >> 5, lane = tid & 31;
    const int mw = warp & 3, ng = warp >> 2;
    const int q = lane & 3, trow = lane >> 2;
    const int RB = 32 * mw + trow;             // rows RB, RB+8, RB+16, RB+24
    const int r0 = blockIdx.x * 128;
    const int b  = r0 >> 10;
    const int cb0 = r0 & (C - 1);
    const int CL = 32 * ng;                    // low-col bundle base

    int* mcount = (int*)(sm + MISC);
    int* mrows  = (int*)(sm + MISC + 16);
    float* self1 = (float*)(sm + MISC + 528);
    float* selfo = (float*)(sm + MISC + 784);
    float* part  = (float*)(sm + MISC + 1040);   // 2 x 128 floats

    const float nw = fminf(fmaxf(nwp[0], 0.1f), 0.9f);
    const int qtb  = qt[b];
    const float bp0 = bp[0];
    float adjAv[4], adjBv[4], eavv[4];
    const float* hpp[4];
#pragma unroll
    for (int ri = 0; ri < 4; ++ri) {
        int row = RB + 8 * ri;                 // ri: 0,1 -> mt0 rows; 2,3 -> mt1 rows
        adjAv[ri] = g_adj[cb0 + row];
        adjBv[ri] = g_adj[C + cb0 + row];
        eavv[ri]  = ea[cb0 + row];
        hpp[ri]   = ht + (size_t)(r0 + row) * 64;
    }

    if (tid == 0) *mcount = 0;
    __syncthreads();
    if (tid < 128 && onehot[(size_t)qtb * C + cb0 + tid] > 0.5f) {
        int p = atomicAdd(mcount, 1);
        mrows[p] = tid;
    }

    // ---- build X = [fp16(clip5 ht) | fp16(clip5 kc)] ----
    {
        int row = tid >> 1, half = tid & 1;
        const float* src = half ? (kc + (size_t)(cb0 + row) * 64) : (ht + (size_t)(r0 + row) * 64);
        uint32_t rowb = smb + XB + (uint32_t)row * RSB + (uint32_t)half * 128;
#pragma unroll
        for (int i = 0; i < 16; ++i) {
            float4 v = ((const float4*)src)[i];
            storeH2(rowb + i * 8,     clip5f(v.x), clip5f(v.y));
            storeH2(rowb + i * 8 + 4, clip5f(v.z), clip5f(v.w));
        }
    }
    prefetchW(smb + W0, GA1, 34816, tid);

    auto stage_sync = [&] { cpa_wait0(); __syncthreads(); };

    float m[8][4];                 // [mt*4+j][e]
    uint32_t rgp[8][2], zgp[8][2]; // packed fp16x2 gates, [mt*4+j][rowpair]
    // X row addresses for this thread's 4 rows
    uint32_t xr[4];
#pragma unroll
    for (int ri = 0; ri < 4; ++ri) xr[ri] = smb + XB + (uint32_t)(RB + 8 * ri) * RSB;

    // ================= S1: nb1_0 | nb1_1 (in-place X) =================
    stage_sync();
    prefetchW(smb + W1, GA2, 34816, tid);
    {
        float d[16][4] = {};
        mma_stage<128>(smb + XB, smb + W0, d, mw, ng, lane);
#pragma unroll
        for (int mt = 0; mt < 2; ++mt)
#pragma unroll
            for (int nb = 0; nb < 8; ++nb) {
                int c = ((nb < 4) ? CL + 8 * nb : 64 + CL + 8 * (nb - 4)) + 2 * q;
                float b0 = bn1[c], b1 = bn1[c + 1];
                float* dv = d[mt * 8 + nb];
                storeH2(xr[2 * mt] + c * 2,     fmaxf(dv[0] + b0, 0.f), fmaxf(dv[1] + b1, 0.f));
                storeH2(xr[2 * mt + 1] + c * 2, fmaxf(dv[2] + b0, 0.f), fmaxf(dv[3] + b1, 0.f));
            }
    }
    // ================= S2: blockdiag nb2 =================
    stage_sync();
    prefetchW(smb + W0, GA3, 17408, tid);
    {
        float d[16][4] = {};
        mma_stage<128>(smb + XB, smb + W1, d, mw, ng, lane);
        float wn = 1.f - nw;
#pragma unroll
        for (int mt = 0; mt < 2; ++mt)
#pragma unroll
            for (int j = 0; j < 4; ++j) {
                int c = CL + 8 * j + 2 * q;
                float b00 = bn2[c], b01 = bn2[c + 1];
                float b10 = bn2[64 + c], b11 = bn2[64 + c + 1];
                float* dl = d[mt * 8 + j];
                float* dh = d[mt * 8 + 4 + j];
#pragma unroll
                for (int e = 0; e < 4; ++e) {
                    int ri = 2 * mt + (e >> 1);
                    float bb0 = (e & 1) ? b01 : b00;
                    float bb1 = (e & 1) ? b11 : b10;
                    float nb0 = fminf(fmaxf(dl[e] + bb0, 0.f), 5.f);
                    float nb1 = fminf(fmaxf(dh[e] + bb1, 0.f), 5.f);
                    float t = clip5f(adjAv[ri] * nb0);
                    m[mt * 4 + j][e] = clip5f(nw * t + wn * adjBv[ri] * nb1);
                }
            }
    }
    // ---- self path for masked rows (rare) ----
    __syncthreads();
    {
        int mc = *mcount;
        for (int mi = 0; mi < mc; ++mi) {
            int rr = mrows[mi];
            if (tid < 64) {
                const float* hrow = ht + (size_t)(r0 + rr) * 64;
                const float* krow = kc + (size_t)(cb0 + rr) * 64;
                float s = bs1[tid];
                for (int i = 0; i < 64; ++i) s = fmaf(hrow[i], Ws1[i * 64 + tid], s);
                for (int i = 0; i < 64; ++i) s = fmaf(krow[i], Ws1[(64 + i) * 64 + tid], s);
                self1[tid] = fmaxf(s, 0.f);
            }
            __syncthreads();
            if (tid < 64) {
                float s = bs2[tid];
                for (int i = 0; i < 64; ++i) s = fmaf(self1[i], Ws2[i * 64 + tid], s);
                selfo[tid] = fminf(fmaxf(s, 0.f), 10.f);
            }
            __syncthreads();
#pragma unroll
            for (int mt = 0; mt < 2; ++mt) {
                if (RB + 16 * mt == rr)
#pragma unroll
                    for (int j = 0; j < 4; ++j) {
                        int c = CL + 8 * j + 2 * q;
                        m[mt * 4 + j][0] = selfo[c];
                        m[mt * 4 + j][1] = selfo[c + 1];
                    }
                if (RB + 16 * mt + 8 == rr)
#pragma unroll
                    for (int j = 0; j < 4; ++j) {
                        int c = CL + 8 * j + 2 * q;
                        m[mt * 4 + j][2] = selfo[c];
                        m[mt * 4 + j][3] = selfo[c + 1];
                    }
            }
            __syncthreads();
        }
    }
    // store m -> X[0:64] (A for S3, K=64 so cols 64..127 unused)
#pragma unroll
    for (int mt = 0; mt < 2; ++mt)
#pragma unroll
        for (int j = 0; j < 4; ++j) {
            int c = CL + 8 * j + 2 * q;
            storeH2(xr[2 * mt] + c * 2,     m[mt * 4 + j][0], m[mt * 4 + j][1]);
            storeH2(xr[2 * mt + 1] + c * 2, m[mt * 4 + j][2], m[mt * 4 + j][3]);
        }
    // ================= S3: We | Wa; X := [res | raw ht] =================
    stage_sync();
    prefetchW(smb + W1, GA4, 34816, tid);
    {
        float d[16][4] = {};
        mma_stage<64>(smb + XB, smb + W0, d, mw, ng, lane);
#pragma unroll
        for (int mt = 0; mt < 2; ++mt)
#pragma unroll
            for (int j = 0; j < 4; ++j) {
                int c = CL + 8 * j + 2 * q;
                float be0 = be[c], be1 = be[c + 1];
                float ba0 = ba[c], ba1 = ba[c + 1];
                float* dl = d[mt * 8 + j];
                float* dh = d[mt * 8 + 4 + j];
                float res[4];
#pragma unroll
                for (int e = 0; e < 4; ++e) {
                    int ri = 2 * mt + (e >> 1);
                    float mv = m[mt * 4 + j][e];
                    float sg = sigmf(dl[e] + ((e & 1) ? be1 : be0));
                    float th = tanhf(dh[e] + ((e & 1) ? ba1 : ba0));
                    res[e] = mv - eavv[ri] * sg * mv + eavv[ri] * th;
                }
                storeH2(xr[2 * mt] + c * 2,     res[0], res[1]);
                storeH2(xr[2 * mt + 1] + c * 2, res[2], res[3]);
                storeH2(xr[2 * mt] + (64 + c) * 2,
                        hpp[2 * mt][c], hpp[2 * mt][c + 1]);
                storeH2(xr[2 * mt + 1] + (64 + c) * 2,
                        hpp[2 * mt + 1][c], hpp[2 * mt + 1][c + 1]);
            }
    }
    // ================= S4: GRU r | z =================
    stage_sync();
    prefetchW(smb + W0, GA5, 34816, tid);
    {
        float d[16][4] = {};
        mma_stage<128>(smb + XB, smb + W1, d, mw, ng, lane);
#pragma unroll
        for (int mt = 0; mt < 2; ++mt)
#pragma unroll
            for (int j = 0; j < 4; ++j) {
                int c = CL + 8 * j + 2 * q;
                float br0 = bih[c] + bhh[c], br1 = bih[c + 1] + bhh[c + 1];
                float bz0 = bih[64 + c] + bhh[64 + c], bz1 = bih[64 + c + 1] + bhh[64 + c + 1];
                float* dl = d[mt * 8 + j];
                float* dh = d[mt * 8 + 4 + j];
                rgp[mt * 4 + j][0] = packH2(sigmf(dl[0] + br0), sigmf(dl[1] + br1));
                rgp[mt * 4 + j][1] = packH2(sigmf(dl[2] + br0), sigmf(dl[3] + br1));
                zgp[mt * 4 + j][0] = packH2(sigmf(dh[0] + bz0), sigmf(dh[1] + bz1));
                zgp[mt * 4 + j][1] = packH2(sigmf(dh[2] + bz0), sigmf(dh[3] + bz1));
            }
    }
    // ================= S5: blockdiag in|hn ; GRU fuse ; partial output dot =================
    stage_sync();
    {
        float d[16][4] = {};
        mma_stage<128>(smb + XB, smb + W0, d, mw, ng, lane);
        float p[4] = {0.f, 0.f, 0.f, 0.f};
#pragma unroll
        for (int mt = 0; mt < 2; ++mt)
#pragma unroll
            for (int j = 0; j < 4; ++j) {
                int c = CL + 8 * j + 2 * q;
                float bi0 = bih[128 + c], bi1 = bih[128 + c + 1];
                float bh0 = bhh[128 + c], bh1 = bhh[128 + c + 1];
                float w0 = Wp[c], w1 = Wp[c + 1];
                float* dl = d[mt * 8 + j];
                float* dh = d[mt * 8 + 4 + j];
                float2 rg0 = __half22float2(*(__half2*)&rgp[mt * 4 + j][0]);
                float2 rg1 = __half22float2(*(__half2*)&rgp[mt * 4 + j][1]);
                float2 zg0 = __half22float2(*(__half2*)&zgp[mt * 4 + j][0]);
                float2 zg1 = __half22float2(*(__half2*)&zgp[mt * 4 + j][1]);
                int ra = 2 * mt, rb_ = 2 * mt + 1;
                float n00 = tanhf(dl[0] + bi0 + rg0.x * (dh[0] + bh0));
                float n01 = tanhf(dl[1] + bi1 + rg0.y * (dh[1] + bh1));
                float n10 = tanhf(dl[2] + bi0 + rg1.x * (dh[2] + bh0));
                float n11 = tanhf(dl[3] + bi1 + rg1.y * (dh[3] + bh1));
                float h00 = (1.f - zg0.x) * n00 + zg0.x * hpp[ra][c];
                float h01 = (1.f - zg0.y) * n01 + zg0.y * hpp[ra][c + 1];
                float h10 = (1.f - zg1.x) * n10 + zg1.x * hpp[rb_][c];
                float h11 = (1.f - zg1.y) * n11 + zg1.y * hpp[rb_][c + 1];
                p[ra] = fmaf(h00, w0, fmaf(h01, w1, p[ra]));
                p[rb_] = fmaf(h10, w0, fmaf(h11, w1, p[rb_]));
            }
        // reduce across the 4 q-lanes sharing each row
#pragma unroll
        for (int ri = 0; ri < 4; ++ri) {
            p[ri] += __shfl_xor_sync(0xffffffffu, p[ri], 1);
            p[ri] += __shfl_xor_sync(0xffffffffu, p[ri], 2);
        }
        if (q == 0) {
#pragma unroll
            for (int ri = 0; ri < 4; ++ri)
                part[ng * 128 + RB + 8 * ri] = p[ri];
        }
    }
    __syncthreads();
    if (tid < 128) out[r0 + tid] = sigmf(part[tid] + part[128 + tid] + bp0);
}

// ---------------- launch -----------------------------------------------------------------
extern "C" void kernel_launch(void* const* d_in, const int* in_sizes, int n_in,
                              void* d_out, int out_size) {
    const int*   qt     = (const int*)d_in[1];
    const float* ht     = (const float*)d_in[2];
    const float* onehot = (const float*)d_in[3];
    const float* kc     = (const float*)d_in[4];
    const float* graphs = (const float*)d_in[5];
    const float* nw     = (const float*)d_in[6];
    const float* Ws1    = (const float*)d_in[7];
    const float* bs1    = (const float*)d_in[8];
    const float* Ws2    = (const float*)d_in[9];
    const float* bs2    = (const float*)d_in[10];
    const float* Wn1    = (const float*)d_in[11];
    const float* bn1    = (const float*)d_in[12];
    const float* Wn2    = (const float*)d_in[13];
    const float* bn2    = (const float*)d_in[14];
    const float* ea     = (const float*)d_in[15];
    const float* We     = (const float*)d_in[16];
    const float* be     = (const float*)d_in[17];
    const float* Wa     = (const float*)d_in[18];
    const float* ba     = (const float*)d_in[19];
    const float* Wih    = (const float*)d_in[20];
    const float* bih    = (const float*)d_in[21];
    const float* Whh    = (const float*)d_in[22];
    const float* bhh    = (const float*)d_in[23];
    const float* Wp     = (const float*)d_in[24];
    const float* bp     = (const float*)d_in[25];
    float* out = (float*)d_out;

    cudaFuncSetAttribute(fused_kernel, cudaFuncAttributeMaxDynamicSharedMemorySize, SMEM_DYN);

    adj_kernel<<<2, 1024>>>(qt, onehot, graphs);
    prep_kernel<<<(73728 + 255) / 256, 256>>>(Wn1, Wn2, We, Wa, Wih, Whh);
    fused_kernel<<<2048, 256, SMEM_DYN>>>(
        qt, ht, onehot, kc, nw, Ws1, bs1, Ws2, bs2, bn1, bn2,
        ea, be, ba, bih, bhh, Wp, bp, out);
}

// round 9
// speedup vs baseline: 1.8202x; 1.8202x over previous
#include <cuda_runtime.h>
#include <cuda_fp16.h>
#include <cstdint>
#include <math.h>

constexpr int C = 1024;

// ---- smem byte offsets ----
constexpr uint32_t XB   = 0;        // X: 128 rows x 272B, in-place all stages
constexpr uint32_t W0   = 34816;    // weight buffer 0
constexpr uint32_t W1   = 69632;    // weight buffer 1
constexpr uint32_t MISC = 104448;
constexpr uint32_t SMEM_DYN = 105504;
constexpr uint32_t RSB = 272;

// ---- weight arena: per-stage fp16 images ----
constexpr uint32_t GA1 = 0;        // nb1_0|nb1_1                 K=128x128 (34816B)
constexpr uint32_t GA2 = 34816;    // compact [Wn2_0 | Wn2_1]     K=64x128  (17408B)
constexpr uint32_t GA3 = 52224;    // We|Wa                       K=64x128  (17408B)
constexpr uint32_t GA4 = 69632;    // GRU r|z                     K=128x128 (34816B)
constexpr uint32_t GA5 = 104448;   // compact [Wih_n | Whh_n]     K=64x128  (17408B)
__device__ __align__(16) unsigned char g_wb[121856];
__device__ float g_adj[2 * C];

__device__ __forceinline__ float clip5f(float v) { return fminf(fmaxf(v, -5.f), 5.f); }
__device__ __forceinline__ float sigmf(float v) {
    return __fdividef(1.f, 1.f + __expf(-v));
}
__device__ __forceinline__ float tanhf_fast(float v) {
    return __fdividef(2.f, 1.f + __expf(-2.f * v)) - 1.f;
}

__device__ __forceinline__ uint32_t smem_u32(const void* p) {
    uint32_t a;
    asm("{ .reg .u64 t; cvta.to.shared.u64 t, %1; cvt.u32.u64 %0, t; }" : "=r"(a) : "l"(p));
    return a;
}
__device__ __forceinline__ void ldsm4(uint32_t* r, uint32_t a) {
    asm volatile("ldmatrix.sync.aligned.m8n8.x4.shared.b16 {%0,%1,%2,%3}, [%4];"
                 : "=r"(r[0]), "=r"(r[1]), "=r"(r[2]), "=r"(r[3]) : "r"(a));
}
__device__ __forceinline__ void ldsm4t(uint32_t* r, uint32_t a) {
    asm volatile("ldmatrix.sync.aligned.m8n8.x4.trans.shared.b16 {%0,%1,%2,%3}, [%4];"
                 : "=r"(r[0]), "=r"(r[1]), "=r"(r[2]), "=r"(r[3]) : "r"(a));
}
__device__ __forceinline__ void mma16816(float* d, const uint32_t* a, const uint32_t* b) {
    asm volatile("mma.sync.aligned.m16n8k16.row.col.f32.f16.f16.f32 "
                 "{%0,%1,%2,%3}, {%4,%5,%6,%7}, {%8,%9}, {%0,%1,%2,%3};"
                 : "+f"(d[0]), "+f"(d[1]), "+f"(d[2]), "+f"(d[3])
                 : "r"(a[0]), "r"(a[1]), "r"(a[2]), "r"(a[3]), "r"(b[0]), "r"(b[1]));
}
__device__ __forceinline__ void cpa16(uint32_t dst, const void* src) {
    asm volatile("cp.async.cg.shared.global [%0], [%1], 16;" :: "r"(dst), "l"(src));
}
__device__ __forceinline__ void cpa_commit() { asm volatile("cp.async.commit_group;" ::: "memory"); }
__device__ __forceinline__ void cpa_wait0()  { asm volatile("cp.async.wait_group 0;" ::: "memory"); }

__device__ __forceinline__ uint32_t packH2(float f0, float f1) {
    uint32_t h;
    asm("cvt.rn.f16x2.f32 %0, %1, %2;" : "=r"(h) : "f"(f1), "f"(f0));
    return h;
}
__device__ __forceinline__ void storeH2(uint32_t addr, float f0, float f1) {
    uint32_t h = packH2(f0, f1);
    asm volatile("st.shared.b32 [%0], %1;" :: "r"(addr), "r"(h));
}

// ---------------- adj precompute (sparse) ------------------------------------------------
__global__ void adj_kernel(const int* __restrict__ qt, const float* __restrict__ onehot,
                           const float* __restrict__ graphs) {
    __shared__ int nnz;
    __shared__ int idxs[1024];
    __shared__ float wts[1024];
    __shared__ float denom;
    int d = threadIdx.x, k = blockIdx.x;
    const float* a0 = onehot + (size_t)qt[0] * C;
    float a = a0[d];
    if (d == 0) nnz = 0;
    __syncthreads();
    if (a != 0.f) { int p = atomicAdd(&nnz, 1); idxs[p] = d; wts[p] = a; }
    __syncthreads();
    if (d == 0) {
        float s = 0.f;
        for (int i = 0; i < nnz; ++i) s += wts[i];
        denom = fmaxf(s, 1.f);
    }
    __syncthreads();
    float s = 0.f;
    int m = nnz;
    for (int i = 0; i < m; ++i)
        s = fmaf(wts[i], graphs[((size_t)k * C + idxs[i]) * C + d], s);
    g_adj[k * C + d] = clip5f(s / denom);
}

// ---------------- weight prep ------------------------------------------------------------
__global__ void prep_kernel(const float* __restrict__ Wn1, const float* __restrict__ Wn2,
                            const float* __restrict__ We,  const float* __restrict__ Wa,
                            const float* __restrict__ Wih, const float* __restrict__ Whh) {
    int i = blockIdx.x * 256 + threadIdx.x;
    if (i >= 57344) return;
    int j; uint32_t base; float w;
    if (i < 16384) {        // S1: nb1_0 | nb1_1, K=128
        j = i; base = GA1;
        int k = j >> 7, n = j & 127;
        if (n < 64) w = Wn1[(size_t)(128 + k) * 64 + n];
        else        w = Wn1[(size_t)(256 + 128 + k) * 64 + (n - 64)];
    } else if (i < 24576) { // S2 compact: [Wn2_0 | Wn2_1], 64 x 128
        j = i - 16384; base = GA2;
        int k = j >> 7, n = j & 127;
        w = (n < 64) ? Wn2[(size_t)k * 64 + n]
                     : Wn2[(size_t)(64 + k) * 64 + (n - 64)];
    } else if (i < 32768) { // S3: We | Wa, 64 x 128
        j = i - 24576; base = GA3;
        int k = j >> 7, n = j & 127;
        w = (n < 64) ? We[(size_t)k * 64 + n] : Wa[(size_t)k * 64 + (n - 64)];
    } else if (i < 49152) { // S4: [Wih_r;Whh_r] | [Wih_z;Whh_z], K=128
        j = i - 32768; base = GA4;
        int k = j >> 7, n = j & 127;
        w = (k < 64) ? Wih[(size_t)k * 192 + n] : Whh[(size_t)(k - 64) * 192 + n];
    } else {                // S5 compact: [Wih_n | Whh_n], 64 x 128
        j = i - 49152; base = GA5;
        int k = j >> 7, n = j & 127;
        w = (n < 64) ? Wih[(size_t)k * 192 + 128 + n]
                     : Whh[(size_t)k * 192 + 128 + (n - 64)];
    }
    int k = j >> 7, n = j & 127;
    *(__half*)(g_wb + base + (uint32_t)k * RSB + n * 2) = __float2half_rn(w);
}

// ---------------- stage GEMM: D[128,128] = A[128,KD] @ W[KD,128], fp16 single pass -------
template <int KD>
__device__ __forceinline__ void mma_stage(uint32_t aBase, uint32_t wbuf,
                                          float d[16][4], int warp, int lane) {
    const int lrow = (lane & 7) + ((lane & 8) ? 8 : 0);
    const int lhi8 = (lane & 16) ? 8 : 0;
    const uint32_t aA = aBase + (uint32_t)(warp * 16 + lrow) * RSB + lhi8 * 2;
    const uint32_t wOff = wbuf + (uint32_t)lrow * RSB + lhi8 * 2;
#pragma unroll
    for (int kc = 0; kc < KD / 16; ++kc) {
        uint32_t a[4];
        ldsm4(a, aA + kc * 32);
#pragma unroll
        for (int half = 0; half < 2; ++half) {
            uint32_t bh[4][4];
#pragma unroll
            for (int p = 0; p < 4; ++p)
                ldsm4t(bh[p], wOff + (uint32_t)kc * 16 * RSB + (4 * half + p) * 32);
#pragma unroll
            for (int n8 = 0; n8 < 8; ++n8)
                mma16816(d[8 * half + n8], a, &bh[n8 >> 1][(n8 & 1) * 2]);
        }
    }
}

// ---- split blockdiag stage: D[:,64h..] = A[:,64h..+64] @ W'[0:64, 64h..], K=64 each -----
__device__ __forceinline__ void mma_split(uint32_t aBase, uint32_t wbuf,
                                          float d[16][4], int warp, int lane) {
    const int lrow = (lane & 7) + ((lane & 8) ? 8 : 0);
    const int lhi8 = (lane & 16) ? 8 : 0;
    const uint32_t aA = aBase + (uint32_t)(warp * 16 + lrow) * RSB + lhi8 * 2;
    const uint32_t wOff = wbuf + (uint32_t)lrow * RSB + lhi8 * 2;
#pragma unroll
    for (int h = 0; h < 2; ++h) {
#pragma unroll
        for (int kc = 0; kc < 4; ++kc) {
            uint32_t a[4];
            ldsm4(a, aA + h * 128 + kc * 32);
            uint32_t bh[4][4];
#pragma unroll
            for (int p = 0; p < 4; ++p)
                ldsm4t(bh[p], wOff + h * 128 + (uint32_t)kc * 16 * RSB + p * 32);
#pragma unroll
            for (int n8 = 0; n8 < 8; ++n8)
                mma16816(d[8 * h + n8], a, &bh[n8 >> 1][(n8 & 1) * 2]);
        }
    }
}

__device__ __forceinline__ void prefetchW(uint32_t dst, uint32_t gsrc, int bytes, int tid) {
    const unsigned char* s = g_wb + gsrc;
    for (int o = tid * 16; o < bytes; o += 256 * 16) cpa16(dst + o, s + o);
    cpa_commit();
}

// ---------------- main fused kernel ------------------------------------------------------
__global__ void __launch_bounds__(256, 2)
fused_kernel(const int* __restrict__ qt, const float* __restrict__ ht,
             const float* __restrict__ onehot, const float* __restrict__ kc,
             const float* __restrict__ nwp,
             const float* __restrict__ Ws1, const float* __restrict__ bs1,
             const float* __restrict__ Ws2, const float* __restrict__ bs2,
             const float* __restrict__ bn1, const float* __restrict__ bn2,
             const float* __restrict__ ea,  const float* __restrict__ be,
             const float* __restrict__ ba,  const float* __restrict__ bih,
             const float* __restrict__ bhh, const float* __restrict__ Wp,
             const float* __restrict__ bp, float* __restrict__ out) {
    extern __shared__ __align__(16) char sm[];
    const uint32_t smb = smem_u32(sm);

    const int tid = threadIdx.x;
    const int warp = tid >> 5, lane = tid & 31;
    const int q = lane & 3, trow = lane >> 2;
    const int R0 = warp * 16 + trow, R1 = R0 + 8;
    const int r0 = blockIdx.x * 128;
    const int b  = r0 >> 10;
    const int cb0 = r0 & (C - 1);

    int* mcount = (int*)(sm + MISC);
    int* mrows  = (int*)(sm + MISC + 16);
    float* self1 = (float*)(sm + MISC + 528);
    float* selfo = (float*)(sm + MISC + 784);

    const float nw = fminf(fmaxf(nwp[0], 0.1f), 0.9f);
    const int qtb  = qt[b];
    const float bp0 = bp[0];
    const float adjA0 = g_adj[cb0 + R0], adjA1 = g_adj[cb0 + R1];
    const float adjB0 = g_adj[C + cb0 + R0], adjB1 = g_adj[C + cb0 + R1];
    const float eav0 = ea[cb0 + R0], eav1 = ea[cb0 + R1];
    const float* hp0 = ht + (size_t)(r0 + R0) * 64;
    const float* hp1 = ht + (size_t)(r0 + R1) * 64;

    if (tid == 0) *mcount = 0;
    __syncthreads();
    if (tid < 128 && onehot[(size_t)qtb * C + cb0 + tid] > 0.5f) {
        int p = atomicAdd(mcount, 1);
        mrows[p] = tid;
    }

    // ---- build X = [fp16(clip5 ht) | fp16(clip5 kc)] ----
    {
        int row = tid >> 1, half = tid & 1;
        const float* src = half ? (kc + (size_t)(cb0 + row) * 64) : (ht + (size_t)(r0 + row) * 64);
        uint32_t rowb = smb + XB + (uint32_t)row * RSB + (uint32_t)half * 128;
#pragma unroll
        for (int i = 0; i < 16; ++i) {
            float4 v = ((const float4*)src)[i];
            storeH2(rowb + i * 8,     clip5f(v.x), clip5f(v.y));
            storeH2(rowb + i * 8 + 4, clip5f(v.z), clip5f(v.w));
        }
    }
    prefetchW(smb + W0, GA1, 34816, tid);

    auto stage_sync = [&] { cpa_wait0(); __syncthreads(); };

    float m[8][4];
    uint32_t rgp[8][2], zgp[8][2];   // packed fp16x2 gates
    const uint32_t x0 = smb + XB + (uint32_t)R0 * RSB, x1 = smb + XB + (uint32_t)R1 * RSB;

    // ================= S1: nb1_0 | nb1_1 (in-place X) =================
    stage_sync();
    prefetchW(smb + W1, GA2, 17408, tid);
    {
        float d[16][4] = {};
        mma_stage<128>(smb + XB, smb + W0, d, warp, lane);
#pragma unroll
        for (int nb = 0; nb < 16; ++nb) {
            int c = 8 * nb + 2 * q;
            float b0 = bn1[c], b1 = bn1[c + 1];
            storeH2(x0 + c * 2, fmaxf(d[nb][0] + b0, 0.f), fmaxf(d[nb][1] + b1, 0.f));
            storeH2(x1 + c * 2, fmaxf(d[nb][2] + b0, 0.f), fmaxf(d[nb][3] + b1, 0.f));
        }
    }
    // ================= S2: split nb2 (two K=64 halves) =================
    stage_sync();
    prefetchW(smb + W0, GA3, 17408, tid);
    {
        float d[16][4] = {};
        mma_split(smb + XB, smb + W1, d, warp, lane);
        float wn = 1.f - nw;
#pragma unroll
        for (int nb = 0; nb < 8; ++nb) {
            int c = 8 * nb + 2 * q;
            float b00 = bn2[c], b01 = bn2[c + 1];
            float b10 = bn2[64 + c], b11 = bn2[64 + c + 1];
#pragma unroll
            for (int e = 0; e < 4; ++e) {
                float adjA = (e < 2) ? adjA0 : adjA1;
                float adjB = (e < 2) ? adjB0 : adjB1;
                float bb0 = (e & 1) ? b01 : b00;
                float bb1 = (e & 1) ? b11 : b10;
                float nb0 = fminf(fmaxf(d[nb][e] + bb0, 0.f), 5.f);
                float nb1 = fminf(fmaxf(d[nb + 8][e] + bb1, 0.f), 5.f);
                float t = clip5f(adjA * nb0);
                m[nb][e] = clip5f(nw * t + wn * adjB * nb1);
            }
        }
    }
    // ---- self path for masked rows (rare) ----
    __syncthreads();
    {
        int mc = *mcount;
        for (int mi = 0; mi < mc; ++mi) {
            int rr = mrows[mi];
            if (tid < 64) {
                const float* hrow = ht + (size_t)(r0 + rr) * 64;
                const float* krow = kc + (size_t)(cb0 + rr) * 64;
                float s = bs1[tid];
                for (int i = 0; i < 64; ++i) s = fmaf(hrow[i], Ws1[i * 64 + tid], s);
                for (int i = 0; i < 64; ++i) s = fmaf(krow[i], Ws1[(64 + i) * 64 + tid], s);
                self1[tid] = fmaxf(s, 0.f);
            }
            __syncthreads();
            if (tid < 64) {
                float s = bs2[tid];
                for (int i = 0; i < 64; ++i) s = fmaf(self1[i], Ws2[i * 64 + tid], s);
                selfo[tid] = fminf(fmaxf(s, 0.f), 10.f);
            }
            __syncthreads();
            if (R0 == rr)
#pragma unroll
                for (int nb = 0; nb < 8; ++nb) {
                    m[nb][0] = selfo[8 * nb + 2 * q];
                    m[nb][1] = selfo[8 * nb + 2 * q + 1];
                }
            if (R1 == rr)
#pragma unroll
                for (int nb = 0; nb < 8; ++nb) {
                    m[nb][2] = selfo[8 * nb + 2 * q];
                    m[nb][3] = selfo[8 * nb + 2 * q + 1];
                }
            __syncthreads();
        }
    }
    // store m -> X[0:64] (A for S3; cols 64..127 stale but unused at K=64)
#pragma unroll
    for (int nb = 0; nb < 8; ++nb) {
        int c = 8 * nb + 2 * q;
        storeH2(x0 + c * 2, m[nb][0], m[nb][1]);
        storeH2(x1 + c * 2, m[nb][2], m[nb][3]);
    }
    // ================= S3: We | Wa; X := [res | raw ht] =================
    stage_sync();
    prefetchW(smb + W1, GA4, 34816, tid);
    {
        float d[16][4] = {};
        mma_stage<64>(smb + XB, smb + W0, d, warp, lane);
#pragma unroll
        for (int nb = 0; nb < 8; ++nb) {
            int c = 8 * nb + 2 * q;
            float be0 = be[c], be1 = be[c + 1];
            float ba0 = ba[c], ba1 = ba[c + 1];
            float res[4];
#pragma unroll
            for (int e = 0; e < 4; ++e) {
                float eav = (e < 2) ? eav0 : eav1;
                float sg = sigmf(d[nb][e] + ((e & 1) ? be1 : be0));
                float th = tanhf_fast(d[nb + 8][e] + ((e & 1) ? ba1 : ba0));
                res[e] = m[nb][e] - eav * sg * m[nb][e] + eav * th;
            }
            storeH2(x0 + c * 2, res[0], res[1]);
            storeH2(x1 + c * 2, res[2], res[3]);
            storeH2(x0 + (64 + c) * 2, hp0[c], hp0[c + 1]);
            storeH2(x1 + (64 + c) * 2, hp1[c], hp1[c + 1]);
        }
    }
    // ================= S4: GRU r | z =================
    stage_sync();
    prefetchW(smb + W0, GA5, 17408, tid);
    {
        float d[16][4] = {};
        mma_stage<128>(smb + XB, smb + W1, d, warp, lane);
#pragma unroll
        for (int nb = 0; nb < 8; ++nb) {
            int c = 8 * nb + 2 * q;
            float br0 = bih[c] + bhh[c], br1 = bih[c + 1] + bhh[c + 1];
            float bz0 = bih[64 + c] + bhh[64 + c], bz1 = bih[64 + c + 1] + bhh[64 + c + 1];
            rgp[nb][0] = packH2(sigmf(d[nb][0] + br0), sigmf(d[nb][1] + br1));
            rgp[nb][1] = packH2(sigmf(d[nb][2] + br0), sigmf(d[nb][3] + br1));
            zgp[nb][0] = packH2(sigmf(d[nb + 8][0] + bz0), sigmf(d[nb + 8][1] + bz1));
            zgp[nb][1] = packH2(sigmf(d[nb + 8][2] + bz0), sigmf(d[nb + 8][3] + bz1));
        }
    }
    // ================= S5: split in|hn ; GRU fuse ; output dot =================
    stage_sync();
    {
        float d[16][4] = {};
        mma_split(smb + XB, smb + W0, d, warp, lane);
        float p0 = 0.f, p1 = 0.f;
#pragma unroll
        for (int nb = 0; nb < 8; ++nb) {
            int c = 8 * nb + 2 * q;
            float bi0 = bih[128 + c], bi1 = bih[128 + c + 1];
            float bh0 = bhh[128 + c], bh1 = bhh[128 + c + 1];
            float w0 = Wp[c], w1 = Wp[c + 1];
            float2 rg0 = __half22float2(*(__half2*)&rgp[nb][0]);
            float2 rg1 = __half22float2(*(__half2*)&rgp[nb][1]);
            float2 zg0 = __half22float2(*(__half2*)&zgp[nb][0]);
            float2 zg1 = __half22float2(*(__half2*)&zgp[nb][1]);
            float n00 = tanhf_fast(d[nb][0] + bi0 + rg0.x * (d[nb + 8][0] + bh0));
            float n01 = tanhf_fast(d[nb][1] + bi1 + rg0.y * (d[nb + 8][1] + bh1));
            float n10 = tanhf_fast(d[nb][2] + bi0 + rg1.x * (d[nb + 8][2] + bh0));
            float n11 = tanhf_fast(d[nb][3] + bi1 + rg1.y * (d[nb + 8][3] + bh1));
            float h00 = (1.f - zg0.x) * n00 + zg0.x * hp0[c];
            float h01 = (1.f - zg0.y) * n01 + zg0.y * hp0[c + 1];
            float h10 = (1.f - zg1.x) * n10 + zg1.x * hp1[c];
            float h11 = (1.f - zg1.y) * n11 + zg1.y * hp1[c + 1];
            p0 = fmaf(h00, w0, fmaf(h01, w1, p0));
            p1 = fmaf(h10, w0, fmaf(h11, w1, p1));
        }
        p0 += __shfl_xor_sync(0xffffffffu, p0, 1);
        p0 += __shfl_xor_sync(0xffffffffu, p0, 2);
        p1 += __shfl_xor_sync(0xffffffffu, p1, 1);
        p1 += __shfl_xor_sync(0xffffffffu, p1, 2);
        if (q == 0) {
            out[r0 + R0] = sigmf(p0 + bp0);
            out[r0 + R1] = sigmf(p1 + bp0);
        }
    }
}

// ---------------- launch -----------------------------------------------------------------
extern "C" void kernel_launch(void* const* d_in, const int* in_sizes, int n_in,
                              void* d_out, int out_size) {
    const int*   qt     = (const int*)d_in[1];
    const float* ht     = (const float*)d_in[2];
    const float* onehot = (const float*)d_in[3];
    const float* kc     = (const float*)d_in[4];
    const float* graphs = (const float*)d_in[5];
    const float* nw     = (const float*)d_in[6];
    const float* Ws1    = (const float*)d_in[7];
    const float* bs1    = (const float*)d_in[8];
    const float* Ws2    = (const float*)d_in[9];
    const float* bs2    = (const float*)d_in[10];
    const float* Wn1    = (const float*)d_in[11];
    const float* bn1    = (const float*)d_in[12];
    const float* Wn2    = (const float*)d_in[13];
    const float* bn2    = (const float*)d_in[14];
    const float* ea     = (const float*)d_in[15];
    const float* We     = (const float*)d_in[16];
    const float* be     = (const float*)d_in[17];
    const float* Wa     = (const float*)d_in[18];
    const float* ba     = (const float*)d_in[19];
    const float* Wih    = (const float*)d_in[20];
    const float* bih    = (const float*)d_in[21];
    const float* Whh    = (const float*)d_in[22];
    const float* bhh    = (const float*)d_in[23];
    const float* Wp     = (const float*)d_in[24];
    const float* bp     = (const float*)d_in[25];
    float* out = (float*)d_out;

    cudaFuncSetAttribute(fused_kernel, cudaFuncAttributeMaxDynamicSharedMemorySize, SMEM_DYN);

    adj_kernel<<<2, 1024>>>(qt, onehot, graphs);
    prep_kernel<<<(57344 + 255) / 256, 256>>>(Wn1, Wn2, We, Wa, Wih, Whh);
    fused_kernel<<<2048, 256, SMEM_DYN>>>(
        qt, ht, onehot, kc, nw, Ws1, bs1, Ws2, bs2, bn1, bn2,
        ea, be, ba, bih, bhh, Wp, bp, out);
}

// round 13
// speedup vs baseline: 2.0149x; 1.1070x over previous
#include <cuda_runtime.h>
#include <cuda_fp16.h>
#include <cstdint>
#include <math.h>

constexpr int C = 1024;

// ---- smem byte offsets ----
constexpr uint32_t XB   = 0;        // X: 128 rows x 272B (S1 A operand only)
constexpr uint32_t W0   = 34816;    // weight buffer 0
constexpr uint32_t W1   = 69632;    // weight buffer 1
constexpr uint32_t MISC = 104448;
constexpr uint32_t SMEM_DYN = 105504;
constexpr uint32_t RSB = 272;

// ---- weight arena: per-stage fp16 images ----
constexpr uint32_t GA1 = 0;        // nb1_0|nb1_1                 128x128 (34816B)
constexpr uint32_t GA2 = 34816;    // compact [Wn2_0 | Wn2_1]     64x128  (17408B)
constexpr uint32_t GA3 = 52224;    // We|Wa                       64x128  (17408B)
constexpr uint32_t GA4 = 69632;    // GRU r|z                     128x128 (34816B)
constexpr uint32_t GA5 = 104448;   // compact [Wih_n | Whh_n]     64x128  (17408B)
__device__ __align__(16) unsigned char g_wb[121856];
__device__ float g_adj[2 * C];

__device__ __forceinline__ float clip5f(float v) { return fminf(fmaxf(v, -5.f), 5.f); }
__device__ __forceinline__ float sigmf(float v) {          // accurate-ish (final output only)
    return __fdividef(1.f, 1.f + __expf(-v));
}
__device__ __forceinline__ float tanh_ap(float x) {        // 1 MUFU
    float y;
    asm("tanh.approx.f32 %0, %1;" : "=f"(y) : "f"(x));
    return y;
}
__device__ __forceinline__ float sigm_ap(float x) {        // 1 MUFU + FMA
    return fmaf(tanh_ap(0.5f * x), 0.5f, 0.5f);
}

__device__ __forceinline__ uint32_t smem_u32(const void* p) {
    uint32_t a;
    asm("{ .reg .u64 t; cvta.to.shared.u64 t, %1; cvt.u32.u64 %0, t; }" : "=r"(a) : "l"(p));
    return a;
}
__device__ __forceinline__ void ldsm4(uint32_t* r, uint32_t a) {
    asm volatile("ldmatrix.sync.aligned.m8n8.x4.shared.b16 {%0,%1,%2,%3}, [%4];"
                 : "=r"(r[0]), "=r"(r[1]), "=r"(r[2]), "=r"(r[3]) : "r"(a));
}
__device__ __forceinline__ void ldsm4t(uint32_t* r, uint32_t a) {
    asm volatile("ldmatrix.sync.aligned.m8n8.x4.trans.shared.b16 {%0,%1,%2,%3}, [%4];"
                 : "=r"(r[0]), "=r"(r[1]), "=r"(r[2]), "=r"(r[3]) : "r"(a));
}
__device__ __forceinline__ void mma16816(float* d, const uint32_t* a, const uint32_t* b) {
    asm volatile("mma.sync.aligned.m16n8k16.row.col.f32.f16.f16.f32 "
                 "{%0,%1,%2,%3}, {%4,%5,%6,%7}, {%8,%9}, {%0,%1,%2,%3};"
                 : "+f"(d[0]), "+f"(d[1]), "+f"(d[2]), "+f"(d[3])
                 : "r"(a[0]), "r"(a[1]), "r"(a[2]), "r"(a[3]), "r"(b[0]), "r"(b[1]));
}
__device__ __forceinline__ void cpa16(uint32_t dst, const void* src) {
    asm volatile("cp.async.cg.shared.global [%0], [%1], 16;" :: "r"(dst), "l"(src));
}
__device__ __forceinline__ void cpa_commit() { asm volatile("cp.async.commit_group;" ::: "memory"); }
__device__ __forceinline__ void cpa_wait0()  { asm volatile("cp.async.wait_group 0;" ::: "memory"); }

__device__ __forceinline__ uint32_t packH2(float f0, float f1) {
    uint32_t h;
    asm("cvt.rn.f16x2.f32 %0, %1, %2;" : "=r"(h) : "f"(f1), "f"(f0));
    return h;
}
__device__ __forceinline__ void storeH2(uint32_t addr, float f0, float f1) {
    uint32_t h = packH2(f0, f1);
    asm volatile("st.shared.b32 [%0], %1;" :: "r"(addr), "r"(h));
}

// one K=16 chunk x 64 cols (8 n8 blocks): wAddr already includes row/col offsets
__device__ __forceinline__ void mma_k16_n64(float (*d8)[4], const uint32_t a[4], uint32_t wAddr) {
#pragma unroll
    for (int p = 0; p < 4; ++p) {
        uint32_t bf[4];
        ldsm4t(bf, wAddr + p * 32);
        mma16816(d8[2 * p],     a, &bf[0]);
        mma16816(d8[2 * p + 1], a, &bf[2]);
    }
}

// ---------------- adj precompute (sparse) ------------------------------------------------
__global__ void adj_kernel(const int* __restrict__ qt, const float* __restrict__ onehot,
                           const float* __restrict__ graphs) {
    __shared__ int nnz;
    __shared__ int idxs[1024];
    __shared__ float wts[1024];
    __shared__ float denom;
    int d = threadIdx.x, k = blockIdx.x;
    const float* a0 = onehot + (size_t)qt[0] * C;
    float a = a0[d];
    if (d == 0) nnz = 0;
    __syncthreads();
    if (a != 0.f) { int p = atomicAdd(&nnz, 1); idxs[p] = d; wts[p] = a; }
    __syncthreads();
    if (d == 0) {
        float s = 0.f;
        for (int i = 0; i < nnz; ++i) s += wts[i];
        denom = fmaxf(s, 1.f);
    }
    __syncthreads();
    float s = 0.f;
    int m = nnz;
    for (int i = 0; i < m; ++i)
        s = fmaf(wts[i], graphs[((size_t)k * C + idxs[i]) * C + d], s);
    g_adj[k * C + d] = clip5f(s / denom);
}

// ---------------- weight prep ------------------------------------------------------------
__global__ void prep_kernel(const float* __restrict__ Wn1, const float* __restrict__ Wn2,
                            const float* __restrict__ We,  const float* __restrict__ Wa,
                            const float* __restrict__ Wih, const float* __restrict__ Whh) {
    int i = blockIdx.x * 256 + threadIdx.x;
    if (i >= 57344) return;
    int j; uint32_t base; float w;
    if (i < 16384) {        // S1: nb1_0 | nb1_1, K=128
        j = i; base = GA1;
        int k = j >> 7, n = j & 127;
        if (n < 64) w = Wn1[(size_t)(128 + k) * 64 + n];
        else        w = Wn1[(size_t)(256 + 128 + k) * 64 + (n - 64)];
    } else if (i < 24576) { // S2 compact: [Wn2_0 | Wn2_1], 64 x 128
        j = i - 16384; base = GA2;
        int k = j >> 7, n = j & 127;
        w = (n < 64) ? Wn2[(size_t)k * 64 + n]
                     : Wn2[(size_t)(64 + k) * 64 + (n - 64)];
    } else if (i < 32768) { // S3: We | Wa, 64 x 128
        j = i - 24576; base = GA3;
        int k = j >> 7, n = j & 127;
        w = (n < 64) ? We[(size_t)k * 64 + n] : Wa[(size_t)k * 64 + (n - 64)];
    } else if (i < 49152) { // S4: [Wih_r;Whh_r] | [Wih_z;Whh_z], K=128
        j = i - 32768; base = GA4;
        int k = j >> 7, n = j & 127;
        w = (k < 64) ? Wih[(size_t)k * 192 + n] : Whh[(size_t)(k - 64) * 192 + n];
    } else {                // S5 compact: [Wih_n | Whh_n], 64 x 128
        j = i - 49152; base = GA5;
        int k = j >> 7, n = j & 127;
        w = (n < 64) ? Wih[(size_t)k * 192 + 128 + n]
                     : Whh[(size_t)k * 192 + 128 + (n - 64)];
    }
    int k = j >> 7, n = j & 127;
    *(__half*)(g_wb + base + (uint32_t)k * RSB + n * 2) = __float2half_rn(w);
}

__device__ __forceinline__ void prefetchW(uint32_t dst, uint32_t gsrc, int bytes, int tid) {
    const unsigned char* s = g_wb + gsrc;
    for (int o = tid * 16; o < bytes; o += 256 * 16) cpa16(dst + o, s + o);
    cpa_commit();
}

// ---------------- main fused kernel ------------------------------------------------------
__global__ void __launch_bounds__(256, 2)
fused_kernel(const int* __restrict__ qt, const float* __restrict__ ht,
             const float* __restrict__ onehot, const float* __restrict__ kc,
             const float* __restrict__ nwp,
             const float* __restrict__ Ws1, const float* __restrict__ bs1,
             const float* __restrict__ Ws2, const float* __restrict__ bs2,
             const float* __restrict__ bn1, const float* __restrict__ bn2,
             const float* __restrict__ ea,  const float* __restrict__ be,
             const float* __restrict__ ba,  const float* __restrict__ bih,
             const float* __restrict__ bhh, const float* __restrict__ Wp,
             const float* __restrict__ bp, float* __restrict__ out) {
    extern __shared__ __align__(16) char sm[];
    const uint32_t smb = smem_u32(sm);

    const int tid = threadIdx.x;
    const int warp = tid >> 5, lane = tid & 31;
    const int q = lane & 3, trow = lane >> 2;
    const int R0 = warp * 16 + trow, R1 = R0 + 8;
    const int r0 = blockIdx.x * 128;
    const int b  = r0 >> 10;
    const int cb0 = r0 & (C - 1);

    const int lrow = (lane & 7) + ((lane & 8) ? 8 : 0);
    const int lhi8 = (lane & 16) ? 8 : 0;
    const uint32_t wRowOff = (uint32_t)lrow * RSB + lhi8 * 2;

    int* mcount = (int*)(sm + MISC);
    int* mrows  = (int*)(sm + MISC + 16);
    float* self1 = (float*)(sm + MISC + 528);
    float* selfo = (float*)(sm + MISC + 784);

    const float nw = fminf(fmaxf(nwp[0], 0.1f), 0.9f);
    const int qtb  = qt[b];
    const float bp0 = bp[0];
    const float adjA0 = g_adj[cb0 + R0], adjA1 = g_adj[cb0 + R1];
    const float adjB0 = g_adj[C + cb0 + R0], adjB1 = g_adj[C + cb0 + R1];
    const float eav0 = ea[cb0 + R0], eav1 = ea[cb0 + R1];
    const float* hp0 = ht + (size_t)(r0 + R0) * 64;
    const float* hp1 = ht + (size_t)(r0 + R1) * 64;

    if (tid == 0) *mcount = 0;
    __syncthreads();
    if (tid < 128 && onehot[(size_t)qtb * C + cb0 + tid] > 0.5f) {
        int p = atomicAdd(mcount, 1);
        mrows[p] = tid;
    }

    // ---- build X = [fp16(clip5 ht) | fp16(clip5 kc)] (S1 A operand) ----
    {
        int row = tid >> 1, half = tid & 1;
        const float* src = half ? (kc + (size_t)(cb0 + row) * 64) : (ht + (size_t)(r0 + row) * 64);
        uint32_t rowb = smb + XB + (uint32_t)row * RSB + (uint32_t)half * 128;
#pragma unroll
        for (int i = 0; i < 16; ++i) {
            float4 v = ((const float4*)src)[i];
            storeH2(rowb + i * 8,     clip5f(v.x), clip5f(v.y));
            storeH2(rowb + i * 8 + 4, clip5f(v.z), clip5f(v.w));
        }
    }
    prefetchW(smb + W0, GA1, 34816, tid);

    auto stage_sync = [&] { cpa_wait0(); __syncthreads(); };

    uint32_t af1[16][2];            // S1 output fragments
    float m[8][4];
    uint32_t afr[8][2], afh[8][2];  // res / raw-ht fragments
    uint32_t rgp[8][2], zgp[8][2];  // packed gates

    // ================= S1: nb1_0 | nb1_1 (A from smem X) =================
    stage_sync();
    prefetchW(smb + W1, GA2, 17408, tid);
    {
        float d[16][4] = {};
        const uint32_t aA = smb + XB + (uint32_t)(warp * 16 + lrow) * RSB + lhi8 * 2;
        const uint32_t wRow = smb + W0 + wRowOff;
#pragma unroll
        for (int kcu = 0; kcu < 8; ++kcu) {
            uint32_t a[4];
            ldsm4(a, aA + kcu * 32);
            mma_k16_n64(d,     a, wRow + (uint32_t)kcu * 16 * RSB);
            mma_k16_n64(d + 8, a, wRow + (uint32_t)kcu * 16 * RSB + 128);
        }
#pragma unroll
        for (int nb = 0; nb < 16; ++nb) {
            int c = 8 * nb + 2 * q;
            float b0 = bn1[c], b1 = bn1[c + 1];
            af1[nb][0] = packH2(fmaxf(d[nb][0] + b0, 0.f), fmaxf(d[nb][1] + b1, 0.f));
            af1[nb][1] = packH2(fmaxf(d[nb][2] + b0, 0.f), fmaxf(d[nb][3] + b1, 0.f));
        }
    }
    // ================= S2: split nb2 (A = af1 regs) =================
    stage_sync();
    prefetchW(smb + W0, GA3, 17408, tid);
    {
        float d[16][4] = {};
        const uint32_t wRow = smb + W1 + wRowOff;
#pragma unroll
        for (int h = 0; h < 2; ++h)
#pragma unroll
            for (int kcu = 0; kcu < 4; ++kcu) {
                uint32_t a[4] = {af1[8 * h + 2 * kcu][0], af1[8 * h + 2 * kcu][1],
                                 af1[8 * h + 2 * kcu + 1][0], af1[8 * h + 2 * kcu + 1][1]};
                mma_k16_n64(&d[8 * h], a, wRow + (uint32_t)h * 128 + (uint32_t)kcu * 16 * RSB);
            }
        float wn = 1.f - nw;
#pragma unroll
        for (int nb = 0; nb < 8; ++nb) {
            int c = 8 * nb + 2 * q;
            float b00 = bn2[c], b01 = bn2[c + 1];
            float b10 = bn2[64 + c], b11 = bn2[64 + c + 1];
#pragma unroll
            for (int e = 0; e < 4; ++e) {
                float adjA = (e < 2) ? adjA0 : adjA1;
                float adjB = (e < 2) ? adjB0 : adjB1;
                float bb0 = (e & 1) ? b01 : b00;
                float bb1 = (e & 1) ? b11 : b10;
                float nb0 = fminf(fmaxf(d[nb][e] + bb0, 0.f), 5.f);
                float nb1 = fminf(fmaxf(d[nb + 8][e] + bb1, 0.f), 5.f);
                float t = clip5f(adjA * nb0);
                m[nb][e] = clip5f(nw * t + wn * adjB * nb1);
            }
        }
    }
    // ---- self path for masked rows (rare) ----
    __syncthreads();
    {
        int mc = *mcount;
        for (int mi = 0; mi < mc; ++mi) {
            int rr = mrows[mi];
            if (tid < 64) {
                const float* hrow = ht + (size_t)(r0 + rr) * 64;
                const float* krow = kc + (size_t)(cb0 + rr) * 64;
                float s = bs1[tid];
                for (int i = 0; i < 64; ++i) s = fmaf(hrow[i], Ws1[i * 64 + tid], s);
                for (int i = 0; i < 64; ++i) s = fmaf(krow[i], Ws1[(64 + i) * 64 + tid], s);
                self1[tid] = fmaxf(s, 0.f);
            }
            __syncthreads();
            if (tid < 64) {
                float s = bs2[tid];
                for (int i = 0; i < 64; ++i) s = fmaf(self1[i], Ws2[i * 64 + tid], s);
                selfo[tid] = fminf(fmaxf(s, 0.f), 10.f);
            }
            __syncthreads();
            if (R0 == rr)
#pragma unroll
                for (int nb = 0; nb < 8; ++nb) {
                    m[nb][0] = selfo[8 * nb + 2 * q];
                    m[nb][1] = selfo[8 * nb + 2 * q + 1];
                }
            if (R1 == rr)
#pragma unroll
                for (int nb = 0; nb < 8; ++nb) {
                    m[nb][2] = selfo[8 * nb + 2 * q];
                    m[nb][3] = selfo[8 * nb + 2 * q + 1];
                }
            __syncthreads();
        }
    }
    // ================= S3: We | Wa (A = m regs); res -> afr =================
    stage_sync();
    prefetchW(smb + W1, GA4, 34816, tid);
    {
        float d[16][4] = {};
        const uint32_t wRow = smb + W0 + wRowOff;
#pragma unroll
        for (int kcu = 0; kcu < 4; ++kcu) {
            uint32_t a[4] = {packH2(m[2 * kcu][0], m[2 * kcu][1]),
                             packH2(m[2 * kcu][2], m[2 * kcu][3]),
                             packH2(m[2 * kcu + 1][0], m[2 * kcu + 1][1]),
                             packH2(m[2 * kcu + 1][2], m[2 * kcu + 1][3])};
            mma_k16_n64(d,     a, wRow + (uint32_t)kcu * 16 * RSB);
            mma_k16_n64(d + 8, a, wRow + (uint32_t)kcu * 16 * RSB + 128);
        }
#pragma unroll
        for (int nb = 0; nb < 8; ++nb) {
            int c = 8 * nb + 2 * q;
            float be0 = be[c], be1 = be[c + 1];
            float ba0 = ba[c], ba1 = ba[c + 1];
            float res[4];
#pragma unroll
            for (int e = 0; e < 4; ++e) {
                float eav = (e < 2) ? eav0 : eav1;
                float sg = sigm_ap(d[nb][e] + ((e & 1) ? be1 : be0));
                float th = tanh_ap(d[nb + 8][e] + ((e & 1) ? ba1 : ba0));
                res[e] = m[nb][e] - eav * sg * m[nb][e] + eav * th;
            }
            afr[nb][0] = packH2(res[0], res[1]);
            afr[nb][1] = packH2(res[2], res[3]);
        }
    }
    // ---- build raw-ht fragments for S4/S5 ----
#pragma unroll
    for (int nb = 0; nb < 8; ++nb) {
        int c = 8 * nb + 2 * q;
        float2 v0 = *(const float2*)(hp0 + c);
        float2 v1 = *(const float2*)(hp1 + c);
        afh[nb][0] = packH2(v0.x, v0.y);
        afh[nb][1] = packH2(v1.x, v1.y);
    }
    // ================= S4: GRU r | z (A = [afr|afh]) =================
    stage_sync();
    prefetchW(smb + W0, GA5, 17408, tid);
    {
        float d[16][4] = {};
        const uint32_t wRow = smb + W1 + wRowOff;
#pragma unroll
        for (int kcu = 0; kcu < 4; ++kcu) {
            uint32_t a[4] = {afr[2 * kcu][0], afr[2 * kcu][1],
                             afr[2 * kcu + 1][0], afr[2 * kcu + 1][1]};
            mma_k16_n64(d,     a, wRow + (uint32_t)kcu * 16 * RSB);
            mma_k16_n64(d + 8, a, wRow + (uint32_t)kcu * 16 * RSB + 128);
        }
#pragma unroll
        for (int kcu = 0; kcu < 4; ++kcu) {
            uint32_t a[4] = {afh[2 * kcu][0], afh[2 * kcu][1],
                             afh[2 * kcu + 1][0], afh[2 * kcu + 1][1]};
            mma_k16_n64(d,     a, wRow + (uint32_t)(kcu + 4) * 16 * RSB);
            mma_k16_n64(d + 8, a, wRow + (uint32_t)(kcu + 4) * 16 * RSB + 128);
        }
#pragma unroll
        for (int nb = 0; nb < 8; ++nb) {
            int c = 8 * nb + 2 * q;
            float br0 = bih[c] + bhh[c], br1 = bih[c + 1] + bhh[c + 1];
            float bz0 = bih[64 + c] + bhh[64 + c], bz1 = bih[64 + c + 1] + bhh[64 + c + 1];
            rgp[nb][0] = packH2(sigm_ap(d[nb][0] + br0), sigm_ap(d[nb][1] + br1));
            rgp[nb][1] = packH2(sigm_ap(d[nb][2] + br0), sigm_ap(d[nb][3] + br1));
            zgp[nb][0] = packH2(sigm_ap(d[nb + 8][0] + bz0), sigm_ap(d[nb + 8][1] + bz1));
            zgp[nb][1] = packH2(sigm_ap(d[nb + 8][2] + bz0), sigm_ap(d[nb + 8][3] + bz1));
        }
    }
    // ================= S5: split in|hn ; GRU fuse ; output dot =================
    stage_sync();
    {
        float d[16][4] = {};
        const uint32_t wRow = smb + W0 + wRowOff;
#pragma unroll
        for (int kcu = 0; kcu < 4; ++kcu) {
            uint32_t a[4] = {afr[2 * kcu][0], afr[2 * kcu][1],
                             afr[2 * kcu + 1][0], afr[2 * kcu + 1][1]};
            mma_k16_n64(d, a, wRow + (uint32_t)kcu * 16 * RSB);
        }
#pragma unroll
        for (int kcu = 0; kcu < 4; ++kcu) {
            uint32_t a[4] = {afh[2 * kcu][0], afh[2 * kcu][1],
                             afh[2 * kcu + 1][0], afh[2 * kcu + 1][1]};
            mma_k16_n64(d + 8, a, wRow + 128 + (uint32_t)kcu * 16 * RSB);
        }
        float p0 = 0.f, p1 = 0.f;
#pragma unroll
        for (int nb = 0; nb < 8; ++nb) {
            int c = 8 * nb + 2 * q;
            float bi0 = bih[128 + c], bi1 = bih[128 + c + 1];
            float bh0 = bhh[128 + c], bh1 = bhh[128 + c + 1];
            float w0 = Wp[c], w1 = Wp[c + 1];
            float2 rg0 = __half22float2(*(__half2*)&rgp[nb][0]);
            float2 rg1 = __half22float2(*(__half2*)&rgp[nb][1]);
            float2 zg0 = __half22float2(*(__half2*)&zgp[nb][0]);
            float2 zg1 = __half22float2(*(__half2*)&zgp[nb][1]);
            float n00 = tanh_ap(d[nb][0] + bi0 + rg0.x * (d[nb + 8][0] + bh0));
            float n01 = tanh_ap(d[nb][1] + bi1 + rg0.y * (d[nb + 8][1] + bh1));
            float n10 = tanh_ap(d[nb][2] + bi0 + rg1.x * (d[nb + 8][2] + bh0));
            float n11 = tanh_ap(d[nb][3] + bi1 + rg1.y * (d[nb + 8][3] + bh1));
            float h00 = (1.f - zg0.x) * n00 + zg0.x * hp0[c];
            float h01 = (1.f - zg0.y) * n01 + zg0.y * hp0[c + 1];
            float h10 = (1.f - zg1.x) * n10 + zg1.x * hp1[c];
            float h11 = (1.f - zg1.y) * n11 + zg1.y * hp1[c + 1];
            p0 = fmaf(h00, w0, fmaf(h01, w1, p0));
            p1 = fmaf(h10, w0, fmaf(h11, w1, p1));
        }
        p0 += __shfl_xor_sync(0xffffffffu, p0, 1);
        p0 += __shfl_xor_sync(0xffffffffu, p0, 2);
        p1 += __shfl_xor_sync(0xffffffffu, p1, 1);
        p1 += __shfl_xor_sync(0xffffffffu, p1, 2);
        if (q == 0) {
            out[r0 + R0] = sigmf(p0 + bp0);
            out[r0 + R1] = sigmf(p1 + bp0);
        }
    }
}

// ---------------- launch -----------------------------------------------------------------
extern "C" void kernel_launch(void* const* d_in, const int* in_sizes, int n_in,
                              void* d_out, int out_size) {
    const int*   qt     = (const int*)d_in[1];
    const float* ht     = (const float*)d_in[2];
    const float* onehot = (const float*)d_in[3];
    const float* kc     = (const float*)d_in[4];
    const float* graphs = (const float*)d_in[5];
    const float* nw     = (const float*)d_in[6];
    const float* Ws1    = (const float*)d_in[7];
    const float* bs1    = (const float*)d_in[8];
    const float* Ws2    = (const float*)d_in[9];
    const float* bs2    = (const float*)d_in[10];
    const float* Wn1    = (const float*)d_in[11];
    const float* bn1    = (const float*)d_in[12];
    const float* Wn2    = (const float*)d_in[13];
    const float* bn2    = (const float*)d_in[14];
    const float* ea     = (const float*)d_in[15];
    const float* We     = (const float*)d_in[16];
    const float* be     = (const float*)d_in[17];
    const float* Wa     = (const float*)d_in[18];
    const float* ba     = (const float*)d_in[19];
    const float* Wih    = (const float*)d_in[20];
    const float* bih    = (const float*)d_in[21];
    const float* Whh    = (const float*)d_in[22];
    const float* bhh    = (const float*)d_in[23];
    const float* Wp     = (const float*)d_in[24];
    const float* bp     = (const float*)d_in[25];
    float* out = (float*)d_out;

    cudaFuncSetAttribute(fused_kernel, cudaFuncAttributeMaxDynamicSharedMemorySize, SMEM_DYN);

    adj_kernel<<<2, 1024>>>(qt, onehot, graphs);
    prep_kernel<<<(57344 + 255) / 256, 256>>>(Wn1, Wn2, We, Wa, Wih, Whh);
    fused_kernel<<<2048, 256, SMEM_DYN>>>(
        qt, ht, onehot, kc, nw, Ws1, bs1, Ws2, bs2, bn1, bn2,
        ea, be, ba, bih, bhh, Wp, bp, out);
}